// round 16
// baseline (speedup 1.0000x reference)
#include <cuda_runtime.h>
#include <cstdint>

#define G        25
#define KIN      15
#define KOUT     3
#define XDIM     (G * KIN)        // 375
#define ODIM     (G * KOUT)       // 75

#define ROWS_PER_TILE  16
#define THREADS        384
#define ROWS_PER_SLOT  (ROWS_PER_TILE / 4)          // 4 rows per warp
#define TILE_FLOATS    (ROWS_PER_TILE * XDIM)       // 6000
#define TILE_BYTES_X   (TILE_FLOATS * 4)            // 24000 (16B-divisible)
#define OUT_FLOATS     (ROWS_PER_TILE * ODIM)       // 1200
#define OUT_F4         (OUT_FLOATS / 4)             // 300
#define STAGES         4
#define SMEM_FLOATS    (STAGES * TILE_FLOATS + OUT_FLOATS)   // 25200
#define SMEM_BYTES     (SMEM_FLOATS * 4)                      // 100800
#define GRID_CTAS      296                           // 2 per SM * 148

// ---- 1D TMA bulk copy: gmem -> smem, completion via mbarrier ----
__device__ __forceinline__ void tma_bulk_1d(uint32_t smem_dst, const void* gmem_src,
                                            uint32_t bytes, uint32_t mbar) {
    asm volatile(
        "cp.async.bulk.shared::cluster.global.mbarrier::complete_tx::bytes "
        "[%0], [%1], %2, [%3];"
        :: "r"(smem_dst), "l"(gmem_src), "r"(bytes), "r"(mbar) : "memory");
}
__device__ __forceinline__ void mbar_init(uint32_t mbar, uint32_t count) {
    asm volatile("mbarrier.init.shared.b64 [%0], %1;" :: "r"(mbar), "r"(count) : "memory");
}
__device__ __forceinline__ void mbar_expect_tx(uint32_t mbar, uint32_t bytes) {
    asm volatile("mbarrier.arrive.expect_tx.shared.b64 _, [%0], %1;"
                 :: "r"(mbar), "r"(bytes) : "memory");
}
__device__ __forceinline__ void mbar_wait(uint32_t mbar, uint32_t parity) {
    asm volatile(
        "{\n\t"
        ".reg .pred p;\n\t"
        "LAB_WAIT_%=:\n\t"
        "mbarrier.try_wait.parity.acquire.cta.shared::cta.b64 p, [%0], %1, 0x989680;\n\t"
        "@!p bra LAB_WAIT_%=;\n\t"
        "}"
        :: "r"(mbar), "r"(parity) : "memory");
}

__global__ __launch_bounds__(THREADS, 2)
void mlp_rsna4_kernel(const float* __restrict__ x,
                      const float* __restrict__ W,
                      const int*   __restrict__ k_idx,
                      const int*   __restrict__ v_idx,
                      float* __restrict__ out,
                      int ntiles)
{
    extern __shared__ float smem[];                 // [STAGES*6000 | 1200] floats
    float* const sxbase = smem;
    float* const sout   = smem + STAGES * TILE_FLOATS;
    __shared__ __align__(8) unsigned long long mbar_storage[STAGES];

    const int tid  = threadIdx.x;
    const int wrp  = tid >> 5;
    const int lane = tid & 31;
    const bool active = (lane < G);
    const int g      = lane;        // group owned by this lane
    const int o_role = wrp >> 2;    // 0..2 : which of the 3 outputs
    const int rslot  = wrp & 3;     // 0..3 : row slot within tile
    const int grid   = (int)gridDim.x;

    uint32_t mb[STAGES], sxa[STAGES];
    #pragma unroll
    for (int s = 0; s < STAGES; s++) {
        mb[s]  = (uint32_t)__cvta_generic_to_shared(&mbar_storage[s]);
        sxa[s] = (uint32_t)__cvta_generic_to_shared(sxbase + s * TILE_FLOATS);
    }

    // ---- Per-thread persistent state: one (g,o) pair (R14 compute) ----
    float wreg[KIN];   // 15
    int   ki[KIN];     // 15
    int   vi_o = 0;
    if (active) {
        #pragma unroll
        for (int i = 0; i < KIN; i++)
            wreg[i] = W[(g * KOUT + o_role) * KIN + i];
        #pragma unroll
        for (int i = 0; i < KIN; i++) ki[i] = k_idx[g * KIN + i];
        vi_o = v_idx[g * KOUT + o_role];
    }

    // ---- Init mbarriers ----
    if (tid == 0) {
        #pragma unroll
        for (int s = 0; s < STAGES; s++) mbar_init(mb[s], 1);
    }
    __syncthreads();   // barriers visible before any TMA targets them

    // ---- Prologue: prefetch tiles t0 .. t0+2*grid into buffers 0..2 ----
    const int tile0 = blockIdx.x;
    if (tid == 0) {
        #pragma unroll
        for (int p = 0; p < STAGES - 1; p++) {
            const int t = tile0 + p * grid;
            if (t < ntiles) {
                mbar_expect_tx(mb[p], TILE_BYTES_X);
                tma_bulk_1d(sxa[p], x + (long long)t * TILE_FLOATS, TILE_BYTES_X, mb[p]);
            }
        }
    }

    // ---- Main loop (R14 body; ring depth 4) ----
    int it = 0;
    for (int tile = tile0; tile < ntiles; tile += grid, it++) {
        const int buf = it & (STAGES - 1);
        const uint32_t parity = (uint32_t)((it >> 2) & 1);

        // Refill the buffer consumed LAST iteration (reads fenced by the
        // trailing __syncthreads of that iteration) with tile+3*grid.
        {
            const int pf = tile + (STAGES - 1) * grid;
            if (tid == 0 && pf < ntiles) {
                const int pb = (buf + STAGES - 1) & (STAGES - 1);
                mbar_expect_tx(mb[pb], TILE_BYTES_X);
                tma_bulk_1d(sxa[pb], x + (long long)pf * TILE_FLOATS,
                            TILE_BYTES_X, mb[pb]);
            }
        }

        // Wait for current tile's TMA delivery
        mbar_wait(mb[buf], parity);

        if (active) {
            const float* __restrict__ xbuf = sxbase + buf * TILE_FLOATS;
            #pragma unroll
            for (int rr = 0; rr < ROWS_PER_SLOT; rr++) {
                const int r = rslot + rr * 4;
                const float* __restrict__ xr = xbuf + r * XDIM;

                float acc = 0.f;
                #pragma unroll
                for (int i = 0; i < KIN; i++)
                    acc = fmaf(xr[ki[i]], wreg[i], acc);   // stride-15: conflict-free

                sout[r * ODIM + vi_o] = acc;               // stride-3: conflict-free
            }
        }

        __syncthreads();          // sout complete

        // Coalesced vectorized flush: 4800 B contiguous span
        {
            const float4* __restrict__ so4 = (const float4*)sout;
            float4* __restrict__ o4 =
                (float4*)(out + (long long)tile * OUT_FLOATS);
            #pragma unroll
            for (int i = tid; i < OUT_F4; i += THREADS)
                o4[i] = so4[i];
        }

        __syncthreads();          // reads of sx[buf]/sout done before reuse
    }
}

extern "C" void kernel_launch(void* const* d_in, const int* in_sizes, int n_in,
                              void* d_out, int out_size)
{
    const float* x     = (const float*)d_in[0];
    const float* W     = (const float*)d_in[1];
    const int*   k_idx = (const int*)d_in[2];
    const int*   v_idx = (const int*)d_in[3];
    float* out = (float*)d_out;

    const int b_rows = in_sizes[0] / XDIM;          // 262144
    const int ntiles = b_rows / ROWS_PER_TILE;      // 16384

    cudaFuncSetAttribute(mlp_rsna4_kernel,
                         cudaFuncAttributeMaxDynamicSharedMemorySize, SMEM_BYTES);

    int grid = GRID_CTAS;
    if (grid > ntiles) grid = ntiles;
    mlp_rsna4_kernel<<<grid, THREADS, SMEM_BYTES>>>(x, W, k_idx, v_idx, out, ntiles);
}

// round 17
// speedup vs baseline: 1.1414x; 1.1414x over previous
#include <cuda_runtime.h>
#include <cstdint>

#define G        25
#define KIN      15
#define KOUT     3
#define XDIM     (G * KIN)        // 375
#define ODIM     (G * KOUT)       // 75

#define ROWS_PER_TILE  16
#define THREADS        384
#define ROWS_PER_SLOT  (ROWS_PER_TILE / 4)          // 4 rows per warp
#define TILE_FLOATS    (ROWS_PER_TILE * XDIM)       // 6000
#define TILE_BYTES_X   (TILE_FLOATS * 4)            // 24000 (16B-divisible)
#define OUT_FLOATS     (ROWS_PER_TILE * ODIM)       // 1200
#define OUT_BYTES      (OUT_FLOATS * 4)             // 4800 (16B-divisible)
#define GRID_CTAS      444                           // 3 per SM * 148

// ---- 1D TMA bulk copy: gmem -> smem, completion via mbarrier ----
__device__ __forceinline__ void tma_bulk_g2s(uint32_t smem_dst, const void* gmem_src,
                                             uint32_t bytes, uint32_t mbar) {
    asm volatile(
        "cp.async.bulk.shared::cluster.global.mbarrier::complete_tx::bytes "
        "[%0], [%1], %2, [%3];"
        :: "r"(smem_dst), "l"(gmem_src), "r"(bytes), "r"(mbar) : "memory");
}
// ---- 1D TMA bulk store: smem -> gmem, bulk_group completion ----
__device__ __forceinline__ void tma_bulk_s2g(void* gmem_dst, uint32_t smem_src,
                                             uint32_t bytes) {
    asm volatile(
        "cp.async.bulk.global.shared::cta.bulk_group [%0], [%1], %2;"
        :: "l"(gmem_dst), "r"(smem_src), "r"(bytes) : "memory");
}
__device__ __forceinline__ void tma_store_commit() {
    asm volatile("cp.async.bulk.commit_group;" ::: "memory");
}
__device__ __forceinline__ void tma_store_wait1() {
    asm volatile("cp.async.bulk.wait_group.read 1;" ::: "memory");
}
__device__ __forceinline__ void tma_store_wait0() {
    asm volatile("cp.async.bulk.wait_group.read 0;" ::: "memory");
}
__device__ __forceinline__ void fence_proxy_async_shared() {
    asm volatile("fence.proxy.async.shared::cta;" ::: "memory");
}
__device__ __forceinline__ void mbar_init(uint32_t mbar, uint32_t count) {
    asm volatile("mbarrier.init.shared.b64 [%0], %1;" :: "r"(mbar), "r"(count) : "memory");
}
__device__ __forceinline__ void mbar_expect_tx(uint32_t mbar, uint32_t bytes) {
    asm volatile("mbarrier.arrive.expect_tx.shared.b64 _, [%0], %1;"
                 :: "r"(mbar), "r"(bytes) : "memory");
}
__device__ __forceinline__ void mbar_wait(uint32_t mbar, uint32_t parity) {
    asm volatile(
        "{\n\t"
        ".reg .pred p;\n\t"
        "LAB_WAIT_%=:\n\t"
        "mbarrier.try_wait.parity.acquire.cta.shared::cta.b64 p, [%0], %1, 0x989680;\n\t"
        "@!p bra LAB_WAIT_%=;\n\t"
        "}"
        :: "r"(mbar), "r"(parity) : "memory");
}

__global__ __launch_bounds__(THREADS, 3)
void mlp_rsna4_kernel(const float* __restrict__ x,
                      const float* __restrict__ W,
                      const int*   __restrict__ k_idx,
                      const int*   __restrict__ v_idx,
                      float* __restrict__ out,
                      int ntiles)
{
    __shared__ float sx[2][TILE_FLOATS];             // 48000 B
    __shared__ float sout[2][OUT_FLOATS];            //  9600 B
    __shared__ __align__(8) unsigned long long mbar_storage[2];

    const int tid  = threadIdx.x;
    const int wrp  = tid >> 5;
    const int lane = tid & 31;
    const bool active = (lane < G);
    const int g      = lane;        // group owned by this lane
    const int o_role = wrp >> 2;    // 0..2 : which of the 3 outputs
    const int rslot  = wrp & 3;     // 0..3 : row slot within tile

    const uint32_t mbar0 = (uint32_t)__cvta_generic_to_shared(&mbar_storage[0]);
    const uint32_t mbar1 = (uint32_t)__cvta_generic_to_shared(&mbar_storage[1]);
    const uint32_t sx0   = (uint32_t)__cvta_generic_to_shared(&sx[0][0]);
    const uint32_t sx1   = (uint32_t)__cvta_generic_to_shared(&sx[1][0]);
    const uint32_t so0   = (uint32_t)__cvta_generic_to_shared(&sout[0][0]);
    const uint32_t so1   = (uint32_t)__cvta_generic_to_shared(&sout[1][0]);

    // ---- Per-thread persistent state: one (g,o) pair (R14 compute) ----
    float wreg[KIN];   // 15
    int   ki[KIN];     // 15
    int   vi_o = 0;
    if (active) {
        #pragma unroll
        for (int i = 0; i < KIN; i++)
            wreg[i] = W[(g * KOUT + o_role) * KIN + i];
        #pragma unroll
        for (int i = 0; i < KIN; i++) ki[i] = k_idx[g * KIN + i];
        vi_o = v_idx[g * KOUT + o_role];
    }

    // ---- Init mbarriers, prefetch first tile into buffer 0 ----
    if (tid == 0) {
        mbar_init(mbar0, 1);
        mbar_init(mbar1, 1);
    }
    __syncthreads();   // barriers visible before any TMA targets them

    int tile = blockIdx.x;
    if (tid == 0 && tile < ntiles) {
        mbar_expect_tx(mbar0, TILE_BYTES_X);
        tma_bulk_g2s(sx0, x + (long long)tile * TILE_FLOATS, TILE_BYTES_X, mbar0);
    }

    // ---- Pipelined grid-stride loop (R14 skeleton; TMA store epilogue) ----
    int it = 0;   // buf = it&1; parity for that mbar = (it>>1)&1
    for (; tile < ntiles; tile += gridDim.x, it++) {
        const int buf = it & 1;
        const uint32_t parity = (it >> 1) & 1;

        // Prefetch next tile into the other x buffer
        const int next = tile + gridDim.x;
        if (tid == 0 && next < ntiles) {
            const uint32_t mb  = buf ? mbar0 : mbar1;
            const uint32_t dst = buf ? sx0   : sx1;
            mbar_expect_tx(mb, TILE_BYTES_X);
            tma_bulk_g2s(dst, x + (long long)next * TILE_FLOATS, TILE_BYTES_X, mb);
        }

        // Wait for current tile's TMA delivery
        mbar_wait(buf ? mbar1 : mbar0, parity);

        if (active) {
            #pragma unroll
            for (int rr = 0; rr < ROWS_PER_SLOT; rr++) {
                const int r = rslot + rr * 4;
                const float* __restrict__ xr = sx[buf] + r * XDIM;

                float acc = 0.f;
                #pragma unroll
                for (int i = 0; i < KIN; i++)
                    acc = fmaf(xr[ki[i]], wreg[i], acc);   // stride-15: conflict-free

                sout[buf][r * ODIM + vi_o] = acc;          // stride-3: conflict-free
            }
        }

        __syncthreads();          // sout[buf] complete

        // Async bulk store of the 4800 B tile output; wait_group 1 keeps at
        // most one store in flight, so sout[buf] (stored 2 tiles ago) is free
        // by the time we compute into it again.
        if (tid == 0) {
            fence_proxy_async_shared();   // order generic smem writes before async read
            tma_bulk_s2g(out + (long long)tile * OUT_FLOATS,
                         buf ? so1 : so0, OUT_BYTES);
            tma_store_commit();
            tma_store_wait1();
        }

        __syncthreads();          // reads of sx[buf] done; store-drain published
    }

    // Drain remaining output stores before exit
    if (tid == 0) tma_store_wait0();
}

extern "C" void kernel_launch(void* const* d_in, const int* in_sizes, int n_in,
                              void* d_out, int out_size)
{
    const float* x     = (const float*)d_in[0];
    const float* W     = (const float*)d_in[1];
    const int*   k_idx = (const int*)d_in[2];
    const int*   v_idx = (const int*)d_in[3];
    float* out = (float*)d_out;

    const int b_rows = in_sizes[0] / XDIM;          // 262144
    const int ntiles = b_rows / ROWS_PER_TILE;      // 16384

    int grid = GRID_CTAS;
    if (grid > ntiles) grid = ntiles;
    mlp_rsna4_kernel<<<grid, THREADS>>>(x, W, k_idx, v_idx, out, ntiles);
}